// round 11
// baseline (speedup 1.0000x reference)
#include <cuda_runtime.h>
#include <math.h>

#define NN      256      // neurons
#define NSAMP   512      // samples
#define NROUND  32       // MAX_SPIKES rounds
#define NSTEP   32       // RK4 steps per round
#define WPS     2        // warps per sample (on different SMSPs)
#define NPER    (NN / (32 * WPS))   // 4 neurons per thread
#define SPB     4        // samples per block (block = 256 threads)

// flattened output offsets (all float32)
#define OUT_TIMES 0
#define OUT_VALS  (NSAMP * NROUND)                       // 16384
#define OUT_MARKS (OUT_VALS + NSAMP * NROUND * NN * 3)   // 12599296

// named barrier across the 2 warps of one sample pair
#define BARP(id) asm volatile("bar.sync %0, 64;" :: "r"(id) : "memory")

// coefficient triple: value = .v * v0 + .i * i0 + .c * icn
struct C3 { float v, i, c; };
__device__ __forceinline__ C3 c3(float a, float b, float c) { return {a, b, c}; }
__device__ __forceinline__ C3 add(C3 a, C3 b) { return {a.v + b.v, a.i + b.i, a.c + b.c}; }
__device__ __forceinline__ C3 sub(C3 a, C3 b) { return {a.v - b.v, a.i - b.i, a.c - b.c}; }
__device__ __forceinline__ C3 scl(float s, C3 a) { return {s * a.v, s * a.i, s * a.c}; }

__device__ __forceinline__ float fast_sigmoid(float x) {
    // 1/(1+exp(-x)) via MUFU.EX2 + MUFU.RCP
    float e = __expf(-x);
    return __fdividef(1.0f, 1.0f + e);
}

__global__ __launch_bounds__(SPB * WPS * 32)
void snn_kernel(const float* __restrict__ ic,      // [256]
                const float* __restrict__ w,       // [256,256]
                const float* __restrict__ mu,      // [2]
                const float* __restrict__ v0g,     // [256]
                const float* __restrict__ i0g,     // [256]
                const float* __restrict__ s0g,     // [512,256]
                const float* __restrict__ reset_s, // [32,512,256]
                const int*   __restrict__ t1p,     // scalar
                float* __restrict__ out)
{
    const int lane = threadIdx.x & 31;
    const int wid  = threadIdx.x >> 5;       // 0..7
    const int pair = wid >> 1;               // 0..3  (sample within block)
    const int half = wid & 1;                // which half of the neurons
    const int samp = blockIdx.x * SPB + pair;

    // vote flags double-buffered by step parity: [pair][parity][half]
    __shared__ int   sh_vote[SPB][2][2];
    // per-round trigger reduction exchange: [pair][half]
    __shared__ float sh_rv[SPB][2], sh_rp[SPB][2];
    __shared__ int   sh_ri[SPB][2], sh_rm[SPB][2];

    const float t1f = (float)(*t1p);
    const float mu1 = mu[0];
    const float mu2 = mu[1];

    // this thread owns neurons n = lane + 32*(half*NPER + j), j in [0,NPER)
    float v[NPER], iC[NPER], s[NPER], icn[NPER];
    #pragma unroll
    for (int j = 0; j < NPER; ++j) {
        const int n = lane + 32 * (half * NPER + j);
        icn[j] = ic[n];
        v[j]   = v0g[n];
        iC[j]  = i0g[n];
        s[j]   = s0g[samp * NN + n];
    }
    float t0s = 0.0f;

    for (int k = 0; k < NROUND; ++k) {
        const float dt = (t1f - t0s) * (1.0f / (float)NSTEP);

        // prefetch the reset row for this round off the critical path
        float rsk[NPER];
        #pragma unroll
        for (int j = 0; j < NPER; ++j)
            rsk[j] = reset_s[(size_t)k * NSAMP * NN + samp * NN + lane + 32 * (half * NPER + j)];

        bool     done = false;
        float    tev  = t1f;
        unsigned emk  = 0;        // per-j spike mask (own neurons)
        int      eidx = 0;

        if (dt > 0.0f) {
            const float h  = dt;
            const float hh = 0.5f * h;
            const float h6 = h * (1.0f / 6.0f);

            // ---- per-round affine RK4 stage coefficients (uniform) ----
            // basis: (v, i, icn).  dv = mu1*(i + icn - v), di = -mu2*i
            const C3 V   = c3(1.f, 0.f, 0.f);
            const C3 I   = c3(0.f, 1.f, 0.f);
            const C3 ONE = c3(0.f, 0.f, 1.f);
            C3 k1v = scl(mu1, sub(add(I, ONE), V));
            C3 k1i = scl(-mu2, I);
            C3 v2c = add(V, scl(hh, k1v));
            C3 i2c = add(I, scl(hh, k1i));
            C3 k2v = scl(mu1, sub(add(i2c, ONE), v2c));
            C3 k2i = scl(-mu2, i2c);
            C3 v3c = add(V, scl(hh, k2v));
            C3 i3c = add(I, scl(hh, k2i));
            C3 k3v = scl(mu1, sub(add(i3c, ONE), v3c));
            C3 k3i = scl(-mu2, i3c);
            C3 v4c = add(V, scl(h, k3v));
            C3 i4c = add(I, scl(h, k3i));
            C3 k4v = scl(mu1, sub(add(i4c, ONE), v4c));
            C3 k4i = scl(-mu2, i4c);
            C3 vnc = add(V, scl(h6, add(add(k1v, k4v), scl(2.f, add(k2v, k3v)))));
            C3 inc = add(I, scl(h6, add(add(k1i, k4i), scl(2.f, add(k2i, k3i)))));
            const float pin = inc.i;   // in2 = pin * iC

            // fold per-neuron icn into per-stage constants
            float v2cc[NPER], v3cc[NPER], v4cc[NPER], vncc[NPER];
            #pragma unroll
            for (int j = 0; j < NPER; ++j) {
                v2cc[j] = v2c.c * icn[j];
                v3cc[j] = v3c.c * icn[j];
                v4cc[j] = v4c.c * icn[j];
                vncc[j] = vnc.c * icn[j];
            }

            float tcur = t0s;
            for (int st = 0; st < NSTEP; ++st) {
                // ---- RK4 step over NPER neurons (register ILP) ----
                float vn[NPER], in2[NPER], sn2[NPER];
                bool mine = false;
                #pragma unroll
                for (int j = 0; j < NPER; ++j) {
                    float v2 = fmaf(v2c.v, v[j], fmaf(v2c.i, iC[j], v2cc[j]));
                    float v3 = fmaf(v3c.v, v[j], fmaf(v3c.i, iC[j], v3cc[j]));
                    float v4 = fmaf(v4c.v, v[j], fmaf(v4c.i, iC[j], v4cc[j]));
                    vn[j]  = fmaf(vnc.v, v[j], fmaf(vnc.i, iC[j], vncc[j]));
                    in2[j] = pin * iC[j];
                    float d1 = fast_sigmoid(v[j]);
                    float d2 = fast_sigmoid(v2);
                    float d3 = fast_sigmoid(v3);
                    float d4 = fast_sigmoid(v4);
                    sn2[j] = fmaf(h6, (d1 + d4) + 2.0f * (d2 + d3), s[j]);
                    mine = mine || (sn2[j] > 0.0f);
                }

                // ---- cross-warp trigger vote: STS + named bar + LDS ----
                const int myvote = __any_sync(0xffffffffu, mine);
                if (lane == 0) sh_vote[pair][st & 1][half] = myvote;
                BARP(pair);
                const int trig = sh_vote[pair][st & 1][0] | sh_vote[pair][st & 1][1];

                if (!trig) {
                    #pragma unroll
                    for (int j = 0; j < NPER; ++j) { v[j] = vn[j]; iC[j] = in2[j]; s[j] = sn2[j]; }
                    tcur += dt;
                    continue;
                }

                // ---- trigger path (once per round) ----
                // local argmax over own NPER neurons (ascending order + strict >
                // keeps lowest index on ties) + local min index with sn2 > 0
                float rv = sn2[0], rp = s[0];
                int   ri = lane + 32 * (half * NPER);
                int   rm = (sn2[0] > 0.0f) ? ri : NN;
                #pragma unroll
                for (int j = 1; j < NPER; ++j) {
                    const int n = lane + 32 * (half * NPER + j);
                    if (sn2[j] > rv) { rv = sn2[j]; rp = s[j]; ri = n; }
                    if (sn2[j] > 0.0f) rm = min(rm, n);
                }
                // warp butterfly
                #pragma unroll
                for (int o = 16; o > 0; o >>= 1) {
                    float ov = __shfl_xor_sync(0xffffffffu, rv, o);
                    float op = __shfl_xor_sync(0xffffffffu, rp, o);
                    int   oi = __shfl_xor_sync(0xffffffffu, ri, o);
                    int   om = __shfl_xor_sync(0xffffffffu, rm, o);
                    if (ov > rv || (ov == rv && oi < ri)) { rv = ov; rp = op; ri = oi; }
                    rm = min(rm, om);
                }
                // cross-warp combine (2 entries)
                if (lane == 0) {
                    sh_rv[pair][half] = rv; sh_rp[pair][half] = rp;
                    sh_ri[pair][half] = ri; sh_rm[pair][half] = rm;
                }
                BARP(pair);
                {
                    float rv0 = sh_rv[pair][0], rp0 = sh_rp[pair][0];
                    int   ri0 = sh_ri[pair][0], rm0 = sh_rm[pair][0];
                    float rv1 = sh_rv[pair][1], rp1 = sh_rp[pair][1];
                    int   ri1 = sh_ri[pair][1], rm1 = sh_rm[pair][1];
                    if (rv1 > rv0 || (rv1 == rv0 && ri1 < ri0)) { rv = rv1; rp = rp1; ri = ri1; }
                    else                                        { rv = rv0; rp = rp0; ri = ri0; }
                    rm = min(rm0, rm1);
                }

                float fr = rp / (rp - rv + 1e-12f);
                fr   = fminf(fmaxf(fr, 0.0f), 1.0f);
                tev  = tcur + fr * dt;
                eidx = rm;
                #pragma unroll
                for (int j = 0; j < NPER; ++j) {
                    v[j]  = v[j]  + fr * (vn[j]  - v[j]);
                    iC[j] = iC[j] + fr * (in2[j] - iC[j]);
                    s[j]  = s[j]  + fr * (sn2[j] - s[j]);
                    if (sn2[j] > 0.0f) emk |= (1u << j);
                }
                done = true;
                break;
            }
        }

        // ---- outputs + reset for this round (state v/iC/s currently == yev) ----
        // issue w-row loads first so their latency overlaps the stores
        float wrow[NPER];
        #pragma unroll
        for (int j = 0; j < NPER; ++j) {
            const int n = lane + 32 * (half * NPER + j);
            wrow[j] = done ? w[eidx * NN + n] : 0.0f;
        }

        if (lane == 0 && half == 0) out[OUT_TIMES + samp * NROUND + k] = tev;
        const size_t base = (size_t)(samp * NROUND + k) * NN;
        #pragma unroll
        for (int j = 0; j < NPER; ++j) {
            const int n = lane + 32 * (half * NPER + j);
            float* vp = out + OUT_VALS + (base + n) * 3;
            vp[0] = v[j]; vp[1] = iC[j]; vp[2] = s[j];
            const bool em = (emk >> j) & 1u;
            out[OUT_MARKS + base + n] = em ? 1.0f : 0.0f;
            v[j]  = v[j] - (em ? 1.0f : 0.0f);
            iC[j] = iC[j] + wrow[j];
            const float srs = em ? rsk[j] : s[j];
            s[j]  = fminf(srs, 0.0f);
        }
        t0s = tev;
    }
}

extern "C" void kernel_launch(void* const* d_in, const int* in_sizes, int n_in,
                              void* d_out, int out_size) {
    const float* ic      = (const float*)d_in[0];  // input_current [256]
    const float* w       = (const float*)d_in[1];  // w [256,256]
    const float* mu      = (const float*)d_in[2];  // mu [2]
    const float* v0      = (const float*)d_in[3];  // v0 [256]
    const float* i0      = (const float*)d_in[4];  // i0 [256]
    const float* s0      = (const float*)d_in[5];  // s0 [512,256]
    const float* reset_s = (const float*)d_in[6];  // reset_s [32,512,256]
    const int*   t1      = (const int*)d_in[7];    // t1 scalar
    float* out = (float*)d_out;

    (void)in_sizes; (void)n_in; (void)out_size;
    snn_kernel<<<NSAMP / SPB, SPB * WPS * 32>>>(ic, w, mu, v0, i0, s0, reset_s, t1, out);
}

// round 13
// speedup vs baseline: 1.2609x; 1.2609x over previous
#include <cuda_runtime.h>
#include <math.h>

#define NN      256      // neurons
#define NSAMP   512      // samples
#define NROUND  32       // MAX_SPIKES rounds
#define NSTEP   32       // RK4 steps per round
#define NPER    8        // neurons per thread
#define WPB     4        // warps (= samples) per block

// flattened output offsets (all float32)
#define OUT_TIMES 0
#define OUT_VALS  (NSAMP * NROUND)                       // 16384
#define OUT_MARKS (OUT_VALS + NSAMP * NROUND * NN * 3)   // 12599296

#define NEG_LOG2E (-1.4426950408889634f)

// coefficient triple: value = .v * v0 + .i * i0 + .c * icn
struct C3 { float v, i, c; };
__device__ __forceinline__ C3 c3(float a, float b, float c) { return {a, b, c}; }
__device__ __forceinline__ C3 add(C3 a, C3 b) { return {a.v + b.v, a.i + b.i, a.c + b.c}; }
__device__ __forceinline__ C3 sub(C3 a, C3 b) { return {a.v - b.v, a.i - b.i, a.c - b.c}; }
__device__ __forceinline__ C3 scl(float s, C3 a) { return {s * a.v, s * a.i, s * a.c}; }

__device__ __forceinline__ float ex2_approx(float x) {
    float r;
    asm("ex2.approx.ftz.f32 %0, %1;" : "=f"(r) : "f"(x));
    return r;
}

__global__ __launch_bounds__(WPB * 32)
void snn_kernel(const float* __restrict__ ic,      // [256]
                const float* __restrict__ w,       // [256,256]
                const float* __restrict__ mu,      // [2]
                const float* __restrict__ v0g,     // [256]
                const float* __restrict__ i0g,     // [256]
                const float* __restrict__ s0g,     // [512,256]
                const float* __restrict__ reset_s, // [32,512,256]
                const int*   __restrict__ t1p,     // scalar
                float* __restrict__ out)
{
    const int lane = threadIdx.x & 31;
    const int wid  = threadIdx.x >> 5;
    const int samp = blockIdx.x * WPB + wid;   // one warp == one sample

    const float t1f = (float)(*t1p);
    const float mu1 = mu[0];
    const float mu2 = mu[1];

    // thread owns neurons lane + 32*j  (coalesced everywhere)
    float v[NPER], iC[NPER], s[NPER], icn[NPER];
    #pragma unroll
    for (int j = 0; j < NPER; ++j) {
        const int n = lane + 32 * j;
        icn[j] = ic[n];
        v[j]   = v0g[n];
        iC[j]  = i0g[n];
        s[j]   = s0g[samp * NN + n];
    }
    float t0s = 0.0f;

    for (int k = 0; k < NROUND; ++k) {
        const float dt = (t1f - t0s) * (1.0f / (float)NSTEP);

        // prefetch the reset row for this round off the critical path
        float rsk[NPER];
        #pragma unroll
        for (int j = 0; j < NPER; ++j)
            rsk[j] = reset_s[(size_t)k * NSAMP * NN + samp * NN + lane + 32 * j];

        bool     done = false;
        float    tev  = t1f;
        unsigned emk  = 0;        // per-j spike mask
        int      eidx = 0;

        if (dt > 0.0f) {
            const float h  = dt;
            const float hh = 0.5f * h;
            const float h6 = h * (1.0f / 6.0f);

            // ---- per-round affine RK4 stage coefficients (warp-uniform) ----
            // basis: (v, i, icn).  dv = mu1*(i + icn - v), di = -mu2*i
            const C3 V   = c3(1.f, 0.f, 0.f);
            const C3 I   = c3(0.f, 1.f, 0.f);
            const C3 ONE = c3(0.f, 0.f, 1.f);
            C3 k1v = scl(mu1, sub(add(I, ONE), V));
            C3 k1i = scl(-mu2, I);
            C3 v2c = add(V, scl(hh, k1v));
            C3 i2c = add(I, scl(hh, k1i));
            C3 k2v = scl(mu1, sub(add(i2c, ONE), v2c));
            C3 k2i = scl(-mu2, i2c);
            C3 v3c = add(V, scl(hh, k2v));
            C3 i3c = add(I, scl(hh, k2i));
            C3 k3v = scl(mu1, sub(add(i3c, ONE), v3c));
            C3 k3i = scl(-mu2, i3c);
            C3 v4c = add(V, scl(h, k3v));
            C3 i4c = add(I, scl(h, k3i));
            C3 k4v = scl(mu1, sub(add(i4c, ONE), v4c));
            C3 k4i = scl(-mu2, i4c);
            C3 vnc = add(V, scl(h6, add(add(k1v, k4v), scl(2.f, add(k2v, k3v)))));
            C3 inc = add(I, scl(h6, add(add(k1i, k4i), scl(2.f, add(k2i, k3i)))));
            const float pin = inc.i;   // in2 = pin * iC

            // stage coeffs for the sigmoid arguments, pre-scaled by -log2(e)
            // so u = -log2e * v_stage feeds ex2 directly: e^{-v_stage} = 2^u
            const float a2 = NEG_LOG2E * v2c.v, b2 = NEG_LOG2E * v2c.i;
            const float a3 = NEG_LOG2E * v3c.v, b3 = NEG_LOG2E * v3c.i;
            const float a4 = NEG_LOG2E * v4c.v, b4 = NEG_LOG2E * v4c.i;
            float u2cc[NPER], u3cc[NPER], u4cc[NPER], vncc[NPER];
            #pragma unroll
            for (int j = 0; j < NPER; ++j) {
                u2cc[j] = (NEG_LOG2E * v2c.c) * icn[j];
                u3cc[j] = (NEG_LOG2E * v3c.c) * icn[j];
                u4cc[j] = (NEG_LOG2E * v4c.c) * icn[j];
                vncc[j] = vnc.c * icn[j];
            }

            float tcur = t0s;
            for (int st = 0; st < NSTEP; ++st) {
                // ---- RK4 step over 8 neurons (pure register ILP) ----
                // sigmoid sum via pairwise combine:
                //   d1+d4 = (t1+t4)/(t1*t4), d2+d3 = (t2+t3)/(t2*t3),
                //   t_i = 1 + 2^{-log2e * v_stage_i}
                // MUFU per neuron: 4 EX2 + 2 RCP (was 4 EX2 + 4 RCP)
                float vn[NPER], in2[NPER], sn2[NPER];
                bool mine = false;
                #pragma unroll
                for (int j = 0; j < NPER; ++j) {
                    float u1 = NEG_LOG2E * v[j];
                    float u2 = fmaf(a2, v[j], fmaf(b2, iC[j], u2cc[j]));
                    float u3 = fmaf(a3, v[j], fmaf(b3, iC[j], u3cc[j]));
                    float u4 = fmaf(a4, v[j], fmaf(b4, iC[j], u4cc[j]));
                    vn[j]  = fmaf(vnc.v, v[j], fmaf(vnc.i, iC[j], vncc[j]));
                    in2[j] = pin * iC[j];
                    float e1 = ex2_approx(u1);
                    float e2 = ex2_approx(u2);
                    float e3 = ex2_approx(u3);
                    float e4 = ex2_approx(u4);
                    float t1_ = 1.0f + e1, t2_ = 1.0f + e2;
                    float t3_ = 1.0f + e3, t4_ = 1.0f + e4;
                    float d14 = __fdividef(t1_ + t4_, t1_ * t4_);
                    float d23 = __fdividef(t2_ + t3_, t2_ * t3_);
                    sn2[j] = fmaf(h6, fmaf(2.0f, d23, d14), s[j]);
                    mine = mine || (sn2[j] > 0.0f);
                }

                // ---- trigger check: single warp vote, no barrier ----
                if (!__any_sync(0xffffffffu, mine)) {
                    #pragma unroll
                    for (int j = 0; j < NPER; ++j) { v[j] = vn[j]; iC[j] = in2[j]; s[j] = sn2[j]; }
                    tcur += dt;
                    continue;
                }

                // ---- trigger path (once per round) ----
                // local argmax over own 8 neurons (ascending j + strict > keeps
                // the lowest index on ties, matching jnp.argmax) + local min
                // index with sn2 > 0
                float rv = sn2[0], rp = s[0];
                int   ri = lane;
                int   rm = (sn2[0] > 0.0f) ? lane : NN;
                #pragma unroll
                for (int j = 1; j < NPER; ++j) {
                    const int n = lane + 32 * j;
                    if (sn2[j] > rv) { rv = sn2[j]; rp = s[j]; ri = n; }
                    if (sn2[j] > 0.0f) rm = min(rm, n);
                }
                // warp butterfly: every lane ends with the full result
                #pragma unroll
                for (int o = 16; o > 0; o >>= 1) {
                    float ov = __shfl_xor_sync(0xffffffffu, rv, o);
                    float op = __shfl_xor_sync(0xffffffffu, rp, o);
                    int   oi = __shfl_xor_sync(0xffffffffu, ri, o);
                    int   om = __shfl_xor_sync(0xffffffffu, rm, o);
                    if (ov > rv || (ov == rv && oi < ri)) { rv = ov; rp = op; ri = oi; }
                    rm = min(rm, om);
                }

                float fr = rp / (rp - rv + 1e-12f);
                fr   = fminf(fmaxf(fr, 0.0f), 1.0f);
                tev  = tcur + fr * dt;
                eidx = rm;
                #pragma unroll
                for (int j = 0; j < NPER; ++j) {
                    v[j]  = v[j]  + fr * (vn[j]  - v[j]);
                    iC[j] = iC[j] + fr * (in2[j] - iC[j]);
                    s[j]  = s[j]  + fr * (sn2[j] - s[j]);
                    if (sn2[j] > 0.0f) emk |= (1u << j);
                }
                done = true;
                break;
            }
        }

        // ---- outputs + reset for this round (state v/iC/s currently == yev) ----
        if (lane == 0) out[OUT_TIMES + samp * NROUND + k] = tev;
        const size_t base = (size_t)(samp * NROUND + k) * NN;
        #pragma unroll
        for (int j = 0; j < NPER; ++j) {
            const int n = lane + 32 * j;
            float* vp = out + OUT_VALS + (base + n) * 3;
            vp[0] = v[j]; vp[1] = iC[j]; vp[2] = s[j];
            const bool em = (emk >> j) & 1u;
            out[OUT_MARKS + base + n] = em ? 1.0f : 0.0f;
            const float wrow = done ? w[eidx * NN + n] : 0.0f;
            v[j]  = v[j] - (em ? 1.0f : 0.0f);
            iC[j] = iC[j] + wrow;
            const float srs = em ? rsk[j] : s[j];
            s[j]  = fminf(srs, 0.0f);
        }
        t0s = tev;
    }
}

extern "C" void kernel_launch(void* const* d_in, const int* in_sizes, int n_in,
                              void* d_out, int out_size) {
    const float* ic      = (const float*)d_in[0];  // input_current [256]
    const float* w       = (const float*)d_in[1];  // w [256,256]
    const float* mu      = (const float*)d_in[2];  // mu [2]
    const float* v0      = (const float*)d_in[3];  // v0 [256]
    const float* i0      = (const float*)d_in[4];  // i0 [256]
    const float* s0      = (const float*)d_in[5];  // s0 [512,256]
    const float* reset_s = (const float*)d_in[6];  // reset_s [32,512,256]
    const int*   t1      = (const int*)d_in[7];    // t1 scalar
    float* out = (float*)d_out;

    (void)in_sizes; (void)n_in; (void)out_size;
    snn_kernel<<<NSAMP / WPB, WPB * 32>>>(ic, w, mu, v0, i0, s0, reset_s, t1, out);
}

// round 14
// speedup vs baseline: 1.2620x; 1.0009x over previous
#include <cuda_runtime.h>
#include <math.h>

#define NN      256      // neurons
#define NSAMP   512      // samples
#define NROUND  32       // MAX_SPIKES rounds
#define NSTEP   32       // RK4 steps per round
#define NPER    8        // neurons per thread
#define WPB     4        // warps (= samples) per block

// flattened output offsets (all float32)
#define OUT_TIMES 0
#define OUT_VALS  (NSAMP * NROUND)                       // 16384
#define OUT_MARKS (OUT_VALS + NSAMP * NROUND * NN * 3)   // 12599296

#define NEG_LOG2E (-1.4426950408889634f)

// coefficient triple: value = .v * v0 + .i * i0 + .c * icn
struct C3 { float v, i, c; };
__device__ __forceinline__ C3 c3(float a, float b, float c) { return {a, b, c}; }
__device__ __forceinline__ C3 add(C3 a, C3 b) { return {a.v + b.v, a.i + b.i, a.c + b.c}; }
__device__ __forceinline__ C3 sub(C3 a, C3 b) { return {a.v - b.v, a.i - b.i, a.c - b.c}; }
__device__ __forceinline__ C3 scl(float s, C3 a) { return {s * a.v, s * a.i, s * a.c}; }

__device__ __forceinline__ float ex2_approx(float x) {
    float r;
    asm("ex2.approx.ftz.f32 %0, %1;" : "=f"(r) : "f"(x));
    return r;
}

__global__ __launch_bounds__(WPB * 32)
void snn_kernel(const float* __restrict__ ic,      // [256]
                const float* __restrict__ w,       // [256,256]
                const float* __restrict__ mu,      // [2]
                const float* __restrict__ v0g,     // [256]
                const float* __restrict__ i0g,     // [256]
                const float* __restrict__ s0g,     // [512,256]
                const float* __restrict__ reset_s, // [32,512,256]
                const int*   __restrict__ t1p,     // scalar
                float* __restrict__ out)
{
    const int lane = threadIdx.x & 31;
    const int wid  = threadIdx.x >> 5;
    const int samp = blockIdx.x * WPB + wid;   // one warp == one sample

    const float t1f = (float)(*t1p);
    const float mu1 = mu[0];
    const float mu2 = mu[1];

    // thread owns neurons lane + 32*j  (coalesced everywhere)
    float v[NPER], iC[NPER], s[NPER], icn[NPER];
    #pragma unroll
    for (int j = 0; j < NPER; ++j) {
        const int n = lane + 32 * j;
        icn[j] = ic[n];
        v[j]   = v0g[n];
        iC[j]  = i0g[n];
        s[j]   = s0g[samp * NN + n];
    }
    float t0s = 0.0f;

    for (int k = 0; k < NROUND; ++k) {
        const float dt = (t1f - t0s) * (1.0f / (float)NSTEP);

        // prefetch the reset row for this round off the critical path
        float rsk[NPER];
        #pragma unroll
        for (int j = 0; j < NPER; ++j)
            rsk[j] = reset_s[(size_t)k * NSAMP * NN + samp * NN + lane + 32 * j];

        bool     done = false;
        float    tev  = t1f;
        unsigned emk  = 0;        // per-j spike mask
        float    wr[NPER];        // w-row contribution (0 unless spiking round)
        #pragma unroll
        for (int j = 0; j < NPER; ++j) wr[j] = 0.0f;

        if (dt > 0.0f) {
            const float h  = dt;
            const float hh = 0.5f * h;
            const float h6 = h * (1.0f / 6.0f);

            // ---- per-round affine RK4 stage coefficients (warp-uniform) ----
            // basis: (v, i, icn).  dv = mu1*(i + icn - v), di = -mu2*i
            const C3 V   = c3(1.f, 0.f, 0.f);
            const C3 I   = c3(0.f, 1.f, 0.f);
            const C3 ONE = c3(0.f, 0.f, 1.f);
            C3 k1v = scl(mu1, sub(add(I, ONE), V));
            C3 k1i = scl(-mu2, I);
            C3 v2c = add(V, scl(hh, k1v));
            C3 i2c = add(I, scl(hh, k1i));
            C3 k2v = scl(mu1, sub(add(i2c, ONE), v2c));
            C3 k2i = scl(-mu2, i2c);
            C3 v3c = add(V, scl(hh, k2v));
            C3 i3c = add(I, scl(hh, k2i));
            C3 k3v = scl(mu1, sub(add(i3c, ONE), v3c));
            C3 k3i = scl(-mu2, i3c);
            C3 v4c = add(V, scl(h, k3v));
            C3 i4c = add(I, scl(h, k3i));
            C3 k4v = scl(mu1, sub(add(i4c, ONE), v4c));
            C3 k4i = scl(-mu2, i4c);
            C3 vnc = add(V, scl(h6, add(add(k1v, k4v), scl(2.f, add(k2v, k3v)))));
            C3 inc = add(I, scl(h6, add(add(k1i, k4i), scl(2.f, add(k2i, k3i)))));
            const float pin = inc.i;   // in2 = pin * iC

            // stage coeffs for the sigmoid arguments, pre-scaled by -log2(e)
            // so u = -log2e * v_stage feeds ex2 directly: e^{-v_stage} = 2^u
            const float a2 = NEG_LOG2E * v2c.v, b2 = NEG_LOG2E * v2c.i;
            const float a3 = NEG_LOG2E * v3c.v, b3 = NEG_LOG2E * v3c.i;
            const float a4 = NEG_LOG2E * v4c.v, b4 = NEG_LOG2E * v4c.i;
            float u2cc[NPER], u3cc[NPER], u4cc[NPER], vncc[NPER];
            #pragma unroll
            for (int j = 0; j < NPER; ++j) {
                u2cc[j] = (NEG_LOG2E * v2c.c) * icn[j];
                u3cc[j] = (NEG_LOG2E * v3c.c) * icn[j];
                u4cc[j] = (NEG_LOG2E * v4c.c) * icn[j];
                vncc[j] = vnc.c * icn[j];
            }

            float tcur = t0s;
            for (int st = 0; st < NSTEP; ++st) {
                // ---- RK4 step over 8 neurons (pure register ILP) ----
                // sigmoid sum d1 + d4 + 2(d2 + d3) via a SINGLE reciprocal:
                //   = [s14*p23 + 2*s23*p14] / (p14*p23)
                //   p14 = t1*t4, p23 = t2*t3, s14 = t1+t4, s23 = t2+t3,
                //   t_i = 1 + 2^{-log2e * v_stage_i}
                // MUFU per neuron: 4 EX2 + 1 RCP (was 4 EX2 + 2 RCP)
                float vn[NPER], in2[NPER], sn2[NPER];
                bool mine = false;
                #pragma unroll
                for (int j = 0; j < NPER; ++j) {
                    float u1 = NEG_LOG2E * v[j];
                    float u2 = fmaf(a2, v[j], fmaf(b2, iC[j], u2cc[j]));
                    float u3 = fmaf(a3, v[j], fmaf(b3, iC[j], u3cc[j]));
                    float u4 = fmaf(a4, v[j], fmaf(b4, iC[j], u4cc[j]));
                    vn[j]  = fmaf(vnc.v, v[j], fmaf(vnc.i, iC[j], vncc[j]));
                    in2[j] = pin * iC[j];
                    float e1 = ex2_approx(u1);
                    float e2 = ex2_approx(u2);
                    float e3 = ex2_approx(u3);
                    float e4 = ex2_approx(u4);
                    float t1_ = 1.0f + e1, t2_ = 1.0f + e2;
                    float t3_ = 1.0f + e3, t4_ = 1.0f + e4;
                    float p14 = t1_ * t4_, p23 = t2_ * t3_;
                    float s14 = t1_ + t4_, s23 = t2_ + t3_;
                    float num = fmaf(s14, p23, (s23 + s23) * p14);
                    float cmb = __fdividef(num, p14 * p23);
                    sn2[j] = fmaf(h6, cmb, s[j]);
                    mine = mine || (sn2[j] > 0.0f);
                }

                // ---- trigger check: single warp vote, no barrier ----
                if (!__any_sync(0xffffffffu, mine)) {
                    #pragma unroll
                    for (int j = 0; j < NPER; ++j) { v[j] = vn[j]; iC[j] = in2[j]; s[j] = sn2[j]; }
                    tcur += dt;
                    continue;
                }

                // ---- trigger path (once per round) ----
                // local argmax over own 8 neurons (ascending j + strict > keeps
                // the lowest index on ties, matching jnp.argmax) + local min
                // index with sn2 > 0
                float rv = sn2[0], rp = s[0];
                int   ri = lane;
                int   rm = (sn2[0] > 0.0f) ? lane : NN;
                #pragma unroll
                for (int j = 1; j < NPER; ++j) {
                    const int n = lane + 32 * j;
                    if (sn2[j] > rv) { rv = sn2[j]; rp = s[j]; ri = n; }
                    if (sn2[j] > 0.0f) rm = min(rm, n);
                }
                // warp butterfly: every lane ends with the full result
                #pragma unroll
                for (int o = 16; o > 0; o >>= 1) {
                    float ov = __shfl_xor_sync(0xffffffffu, rv, o);
                    float op = __shfl_xor_sync(0xffffffffu, rp, o);
                    int   oi = __shfl_xor_sync(0xffffffffu, ri, o);
                    int   om = __shfl_xor_sync(0xffffffffu, rm, o);
                    if (ov > rv || (ov == rv && oi < ri)) { rv = ov; rp = op; ri = oi; }
                    rm = min(rm, om);
                }

                // issue the w-row loads NOW (L2-hot, ~260 cyc) so their latency
                // hides under the frac math + output stores below
                #pragma unroll
                for (int j = 0; j < NPER; ++j)
                    wr[j] = w[rm * NN + lane + 32 * j];

                float fr = rp / (rp - rv + 1e-12f);
                fr   = fminf(fmaxf(fr, 0.0f), 1.0f);
                tev  = tcur + fr * dt;
                #pragma unroll
                for (int j = 0; j < NPER; ++j) {
                    v[j]  = v[j]  + fr * (vn[j]  - v[j]);
                    iC[j] = iC[j] + fr * (in2[j] - iC[j]);
                    s[j]  = s[j]  + fr * (sn2[j] - s[j]);
                    if (sn2[j] > 0.0f) emk |= (1u << j);
                }
                done = true;
                break;
            }
        }
        (void)done;

        // ---- outputs + reset for this round (state v/iC/s currently == yev) ----
        if (lane == 0) out[OUT_TIMES + samp * NROUND + k] = tev;
        const size_t base = (size_t)(samp * NROUND + k) * NN;
        #pragma unroll
        for (int j = 0; j < NPER; ++j) {
            const int n = lane + 32 * j;
            float* vp = out + OUT_VALS + (base + n) * 3;
            vp[0] = v[j]; vp[1] = iC[j]; vp[2] = s[j];
            const bool em = (emk >> j) & 1u;
            out[OUT_MARKS + base + n] = em ? 1.0f : 0.0f;
            v[j]  = v[j] - (em ? 1.0f : 0.0f);
            iC[j] = iC[j] + wr[j];
            const float srs = em ? rsk[j] : s[j];
            s[j]  = fminf(srs, 0.0f);
        }
        t0s = tev;
    }
}

extern "C" void kernel_launch(void* const* d_in, const int* in_sizes, int n_in,
                              void* d_out, int out_size) {
    const float* ic      = (const float*)d_in[0];  // input_current [256]
    const float* w       = (const float*)d_in[1];  // w [256,256]
    const float* mu      = (const float*)d_in[2];  // mu [2]
    const float* v0      = (const float*)d_in[3];  // v0 [256]
    const float* i0      = (const float*)d_in[4];  // i0 [256]
    const float* s0      = (const float*)d_in[5];  // s0 [512,256]
    const float* reset_s = (const float*)d_in[6];  // reset_s [32,512,256]
    const int*   t1      = (const int*)d_in[7];    // t1 scalar
    float* out = (float*)d_out;

    (void)in_sizes; (void)n_in; (void)out_size;
    snn_kernel<<<NSAMP / WPB, WPB * 32>>>(ic, w, mu, v0, i0, s0, reset_s, t1, out);
}

// round 16
// speedup vs baseline: 1.3397x; 1.0616x over previous
#include <cuda_runtime.h>
#include <math.h>

#define NN      256      // neurons
#define NSAMP   512      // samples
#define NROUND  32       // MAX_SPIKES rounds
#define NSTEP   32       // RK4 steps per round
#define NPER    8        // neurons per thread
#define NPAIR   4        // f32x2 pairs per thread
#define WPB     4        // warps (= samples) per block

// flattened output offsets (all float32)
#define OUT_TIMES 0
#define OUT_VALS  (NSAMP * NROUND)                       // 16384
#define OUT_MARKS (OUT_VALS + NSAMP * NROUND * NN * 3)   // 12599296

#define NEG_LOG2E (-1.4426950408889634f)

typedef unsigned long long u64;

// ---- packed f32x2 primitives (element-wise IEEE rn == scalar ops) ----
__device__ __forceinline__ u64 pk2(float lo, float hi) {
    u64 r;
    asm("mov.b64 %0, {%1, %2};" : "=l"(r)
        : "r"(__float_as_uint(lo)), "r"(__float_as_uint(hi)));
    return r;
}
__device__ __forceinline__ void upk2(u64 p, float& lo, float& hi) {
    unsigned a, b;
    asm("mov.b64 {%0, %1}, %2;" : "=r"(a), "=r"(b) : "l"(p));
    lo = __uint_as_float(a); hi = __uint_as_float(b);
}
__device__ __forceinline__ u64 fma2(u64 a, u64 b, u64 c) {
    u64 r; asm("fma.rn.f32x2 %0, %1, %2, %3;" : "=l"(r) : "l"(a), "l"(b), "l"(c)); return r;
}
__device__ __forceinline__ u64 mul2(u64 a, u64 b) {
    u64 r; asm("mul.rn.f32x2 %0, %1, %2;" : "=l"(r) : "l"(a), "l"(b)); return r;
}
__device__ __forceinline__ u64 add2(u64 a, u64 b) {
    u64 r; asm("add.rn.f32x2 %0, %1, %2;" : "=l"(r) : "l"(a), "l"(b)); return r;
}

__device__ __forceinline__ float ex2_approx(float x) {
    float r;
    asm("ex2.approx.ftz.f32 %0, %1;" : "=f"(r) : "f"(x));
    return r;
}

// coefficient triple: value = .v * v0 + .i * i0 + .c * icn
struct C3 { float v, i, c; };
__device__ __forceinline__ C3 c3(float a, float b, float c) { return {a, b, c}; }
__device__ __forceinline__ C3 add(C3 a, C3 b) { return {a.v + b.v, a.i + b.i, a.c + b.c}; }
__device__ __forceinline__ C3 sub(C3 a, C3 b) { return {a.v - b.v, a.i - b.i, a.c - b.c}; }
__device__ __forceinline__ C3 scl(float s, C3 a) { return {s * a.v, s * a.i, s * a.c}; }

__global__ __launch_bounds__(WPB * 32)
void snn_kernel(const float* __restrict__ ic,      // [256]
                const float* __restrict__ w,       // [256,256]
                const float* __restrict__ mu,      // [2]
                const float* __restrict__ v0g,     // [256]
                const float* __restrict__ i0g,     // [256]
                const float* __restrict__ s0g,     // [512,256]
                const float* __restrict__ reset_s, // [32,512,256]
                const int*   __restrict__ t1p,     // scalar
                float* __restrict__ out)
{
    const int lane = threadIdx.x & 31;
    const int wid  = threadIdx.x >> 5;
    const int samp = blockIdx.x * WPB + wid;   // one warp == one sample

    const float t1f = (float)(*t1p);
    const float mu1 = mu[0];
    const float mu2 = mu[1];

    // thread owns neurons n = lane + 32*j, j in [0,8); pair q holds j = 2q, 2q+1
    float icn[NPER];
    float v[NPER], iC[NPER], s[NPER];
    #pragma unroll
    for (int j = 0; j < NPER; ++j) {
        const int n = lane + 32 * j;
        icn[j] = ic[n];
        v[j]   = v0g[n];
        iC[j]  = i0g[n];
        s[j]   = s0g[samp * NN + n];
    }
    // packed state
    u64 vP[NPAIR], iP[NPAIR], sP[NPAIR];
    #pragma unroll
    for (int q = 0; q < NPAIR; ++q) {
        vP[q] = pk2(v[2*q], v[2*q+1]);
        iP[q] = pk2(iC[2*q], iC[2*q+1]);
        sP[q] = pk2(s[2*q], s[2*q+1]);
    }
    float t0s = 0.0f;

    for (int k = 0; k < NROUND; ++k) {
        const float dt = (t1f - t0s) * (1.0f / (float)NSTEP);

        // prefetch the reset row for this round off the critical path
        float rsk[NPER];
        #pragma unroll
        for (int j = 0; j < NPER; ++j)
            rsk[j] = reset_s[(size_t)k * NSAMP * NN + samp * NN + lane + 32 * j];

        int      trig = 0;
        float    tev  = t1f;
        unsigned emk  = 0;
        float    wr[NPER];
        #pragma unroll
        for (int j = 0; j < NPER; ++j) wr[j] = 0.0f;

        u64 vnP[NPAIR], inP[NPAIR], snP[NPAIR];
        float tcur = t0s;

        if (dt > 0.0f) {
            const float h  = dt;
            const float hh = 0.5f * h;
            const float h6 = h * (1.0f / 6.0f);

            // ---- per-round affine RK4 stage coefficients (warp-uniform) ----
            const C3 V   = c3(1.f, 0.f, 0.f);
            const C3 I   = c3(0.f, 1.f, 0.f);
            const C3 ONE = c3(0.f, 0.f, 1.f);
            C3 k1v = scl(mu1, sub(add(I, ONE), V));
            C3 k1i = scl(-mu2, I);
            C3 v2c = add(V, scl(hh, k1v));
            C3 i2c = add(I, scl(hh, k1i));
            C3 k2v = scl(mu1, sub(add(i2c, ONE), v2c));
            C3 k2i = scl(-mu2, i2c);
            C3 v3c = add(V, scl(hh, k2v));
            C3 i3c = add(I, scl(hh, k2i));
            C3 k3v = scl(mu1, sub(add(i3c, ONE), v3c));
            C3 k3i = scl(-mu2, i3c);
            C3 v4c = add(V, scl(h, k3v));
            C3 i4c = add(I, scl(h, k3i));
            C3 k4v = scl(mu1, sub(add(i4c, ONE), v4c));
            C3 k4i = scl(-mu2, i4c);
            C3 vnc = add(V, scl(h6, add(add(k1v, k4v), scl(2.f, add(k2v, k3v)))));
            C3 inc = add(I, scl(h6, add(add(k1i, k4i), scl(2.f, add(k2i, k3i)))));
            const float pin = inc.i;

            const float a2 = NEG_LOG2E * v2c.v, b2 = NEG_LOG2E * v2c.i;
            const float a3 = NEG_LOG2E * v3c.v, b3 = NEG_LOG2E * v3c.i;
            const float a4 = NEG_LOG2E * v4c.v, b4 = NEG_LOG2E * v4c.i;

            // packed broadcast constants
            const u64 A2 = pk2(a2, a2), B2 = pk2(b2, b2);
            const u64 A3 = pk2(a3, a3), B3 = pk2(b3, b3);
            const u64 A4 = pk2(a4, a4), B4 = pk2(b4, b4);
            const u64 VNV = pk2(vnc.v, vnc.v), VNI = pk2(vnc.i, vnc.i);
            const u64 PIN = pk2(pin, pin);
            const u64 NL  = pk2(NEG_LOG2E, NEG_LOG2E);
            const u64 ONE2 = pk2(1.0f, 1.0f);
            const u64 H6P  = pk2(h6, h6);

            u64 U2CC[NPAIR], U3CC[NPAIR], U4CC[NPAIR], VNCC[NPAIR];
            const float c2 = NEG_LOG2E * v2c.c, cc3 = NEG_LOG2E * v3c.c;
            const float c4 = NEG_LOG2E * v4c.c;
            #pragma unroll
            for (int q = 0; q < NPAIR; ++q) {
                U2CC[q] = pk2(c2 * icn[2*q],    c2 * icn[2*q+1]);
                U3CC[q] = pk2(cc3 * icn[2*q],   cc3 * icn[2*q+1]);
                U4CC[q] = pk2(c4 * icn[2*q],    c4 * icn[2*q+1]);
                VNCC[q] = pk2(vnc.c * icn[2*q], vnc.c * icn[2*q+1]);
            }

            for (int st = 0; st < NSTEP; ++st) {
                float mx = -INFINITY;
                #pragma unroll
                for (int q = 0; q < NPAIR; ++q) {
                    const u64 vq = vP[q], iq = iP[q];
                    u64 u1 = mul2(NL, vq);
                    u64 u2 = fma2(A2, vq, fma2(B2, iq, U2CC[q]));
                    u64 u3 = fma2(A3, vq, fma2(B3, iq, U3CC[q]));
                    u64 u4 = fma2(A4, vq, fma2(B4, iq, U4CC[q]));
                    vnP[q] = fma2(VNV, vq, fma2(VNI, iq, VNCC[q]));
                    inP[q] = mul2(PIN, iq);
                    float x1a, x1b, x2a, x2b, x3a, x3b, x4a, x4b;
                    upk2(u1, x1a, x1b); upk2(u2, x2a, x2b);
                    upk2(u3, x3a, x3b); upk2(u4, x4a, x4b);
                    u64 e1 = pk2(ex2_approx(x1a), ex2_approx(x1b));
                    u64 e2 = pk2(ex2_approx(x2a), ex2_approx(x2b));
                    u64 e3 = pk2(ex2_approx(x3a), ex2_approx(x3b));
                    u64 e4 = pk2(ex2_approx(x4a), ex2_approx(x4b));
                    u64 t1_ = add2(ONE2, e1), t2_ = add2(ONE2, e2);
                    u64 t3_ = add2(ONE2, e3), t4_ = add2(ONE2, e4);
                    u64 p14 = mul2(t1_, t4_), p23 = mul2(t2_, t3_);
                    u64 s14 = add2(t1_, t4_), s23 = add2(t2_, t3_);
                    u64 num = fma2(s14, p23, mul2(add2(s23, s23), p14));
                    u64 den = mul2(p14, p23);
                    float na, nb, da, db;
                    upk2(num, na, nb); upk2(den, da, db);
                    float ca = __fdividef(na, da);
                    float cb = __fdividef(nb, db);
                    u64 snq = fma2(H6P, pk2(ca, cb), sP[q]);
                    snP[q] = snq;
                    float sa, sb;
                    upk2(snq, sa, sb);
                    mx = fmaxf(mx, fmaxf(sa, sb));
                }

                // ---- trigger check: single warp vote, no barrier ----
                trig = __any_sync(0xffffffffu, mx > 0.0f);
                if (trig) break;
                #pragma unroll
                for (int q = 0; q < NPAIR; ++q) { vP[q] = vnP[q]; iP[q] = inP[q]; sP[q] = snP[q]; }
                tcur += dt;
            }
        }

        // ---- scalarize state (prev) ----
        #pragma unroll
        for (int q = 0; q < NPAIR; ++q) {
            upk2(vP[q], v[2*q], v[2*q+1]);
            upk2(iP[q], iC[2*q], iC[2*q+1]);
            upk2(sP[q], s[2*q], s[2*q+1]);
        }

        if (trig) {
            float vn[NPER], in2[NPER], sn2[NPER];
            #pragma unroll
            for (int q = 0; q < NPAIR; ++q) {
                upk2(vnP[q], vn[2*q], vn[2*q+1]);
                upk2(inP[q], in2[2*q], in2[2*q+1]);
                upk2(snP[q], sn2[2*q], sn2[2*q+1]);
            }

            // local argmax over own 8 neurons (ascending j + strict > keeps the
            // lowest index on ties, matching jnp.argmax) + local min spiking idx
            float rv = sn2[0], rp = s[0];
            int   ri = lane;
            int   rm = (sn2[0] > 0.0f) ? lane : NN;
            #pragma unroll
            for (int j = 1; j < NPER; ++j) {
                const int n = lane + 32 * j;
                if (sn2[j] > rv) { rv = sn2[j]; rp = s[j]; ri = n; }
                if (sn2[j] > 0.0f) rm = min(rm, n);
            }
            // warp butterfly: every lane ends with the full result
            #pragma unroll
            for (int o = 16; o > 0; o >>= 1) {
                float ov = __shfl_xor_sync(0xffffffffu, rv, o);
                float op = __shfl_xor_sync(0xffffffffu, rp, o);
                int   oi = __shfl_xor_sync(0xffffffffu, ri, o);
                int   om = __shfl_xor_sync(0xffffffffu, rm, o);
                if (ov > rv || (ov == rv && oi < ri)) { rv = ov; rp = op; ri = oi; }
                rm = min(rm, om);
            }

            // issue the w-row loads NOW (L2-hot) so their latency hides under
            // the frac math + output stores below
            #pragma unroll
            for (int j = 0; j < NPER; ++j)
                wr[j] = w[rm * NN + lane + 32 * j];

            float fr = rp / (rp - rv + 1e-12f);
            fr  = fminf(fmaxf(fr, 0.0f), 1.0f);
            tev = tcur + fr * dt;
            #pragma unroll
            for (int j = 0; j < NPER; ++j) {
                v[j]  = v[j]  + fr * (vn[j]  - v[j]);
                iC[j] = iC[j] + fr * (in2[j] - iC[j]);
                s[j]  = s[j]  + fr * (sn2[j] - s[j]);
                if (sn2[j] > 0.0f) emk |= (1u << j);
            }
        }

        // ---- outputs + reset for this round (v/iC/s currently == yev) ----
        if (lane == 0) out[OUT_TIMES + samp * NROUND + k] = tev;
        const size_t base = (size_t)(samp * NROUND + k) * NN;
        #pragma unroll
        for (int j = 0; j < NPER; ++j) {
            const int n = lane + 32 * j;
            float* vp = out + OUT_VALS + (base + n) * 3;
            vp[0] = v[j]; vp[1] = iC[j]; vp[2] = s[j];
            const bool em = (emk >> j) & 1u;
            out[OUT_MARKS + base + n] = em ? 1.0f : 0.0f;
            v[j]  = v[j] - (em ? 1.0f : 0.0f);
            iC[j] = iC[j] + wr[j];
            const float srs = em ? rsk[j] : s[j];
            s[j]  = fminf(srs, 0.0f);
        }
        // repack state for next round
        #pragma unroll
        for (int q = 0; q < NPAIR; ++q) {
            vP[q] = pk2(v[2*q], v[2*q+1]);
            iP[q] = pk2(iC[2*q], iC[2*q+1]);
            sP[q] = pk2(s[2*q], s[2*q+1]);
        }
        t0s = tev;
    }
}

extern "C" void kernel_launch(void* const* d_in, const int* in_sizes, int n_in,
                              void* d_out, int out_size) {
    const float* ic      = (const float*)d_in[0];  // input_current [256]
    const float* w       = (const float*)d_in[1];  // w [256,256]
    const float* mu      = (const float*)d_in[2];  // mu [2]
    const float* v0      = (const float*)d_in[3];  // v0 [256]
    const float* i0      = (const float*)d_in[4];  // i0 [256]
    const float* s0      = (const float*)d_in[5];  // s0 [512,256]
    const float* reset_s = (const float*)d_in[6];  // reset_s [32,512,256]
    const int*   t1      = (const int*)d_in[7];    // t1 scalar
    float* out = (float*)d_out;

    (void)in_sizes; (void)n_in; (void)out_size;
    snn_kernel<<<NSAMP / WPB, WPB * 32>>>(ic, w, mu, v0, i0, s0, reset_s, t1, out);
}